// round 12
// baseline (speedup 1.0000x reference)
#include <cuda_runtime.h>
#include <cuda_fp16.h>
#include <cstdint>

#define NTHREADS 256
#define TILE_B   16
#define NBLOCKS  (4096 / TILE_B)   // 256

// smem layout (bytes)
#define XS_BUFB 4352               // 16 rows * 68 floats * 4B
#define OFB_XS  0                  // 8 warps * 2 bufs * 4352 = 69632
#define OFB_H1  69632              // half [16][1032] = 33024
#define OFB_H2  102656             // half [16][136]  = 4352
#define SMEM_BYTES 107008
#define SH1_STRB 2064
#define SH2_STRB 272
#define XROW_F  68                 // padded floats per staged row

// Fragment-ordered weights
__device__ __align__(16) uint2  g_W0f[512 * 32];     // folded Wg*W0, b-frag order
__device__ __align__(16) float4 g_c0f[512 * 4];      // bias c0 in c-frag order
__device__ __align__(16) uint4  g_W1f[64 * 32 * 8];
__device__ __align__(16) uint4  g_W2f[8 * 32 * 8];
__device__ __align__(16) uint4  g_W3f[32 * 8];

__device__ __forceinline__ float sigmoidf_(float v) {
    float t;
    asm("tanh.approx.f32 %0, %1;" : "=f"(t) : "f"(v * 0.5f));
    return fmaf(t, 0.5f, 0.5f);
}
__device__ __forceinline__ unsigned h2bits(__half2 h) { return *(unsigned*)&h; }

__device__ __forceinline__ void mma16816(float& c0, float& c1, float& c2, float& c3,
                                         unsigned a0, unsigned a1, unsigned a2, unsigned a3,
                                         unsigned b0, unsigned b1) {
    asm("mma.sync.aligned.m16n8k16.row.col.f32.f16.f16.f32 "
        "{%0,%1,%2,%3},{%4,%5,%6,%7},{%8,%9},{%0,%1,%2,%3};"
        : "+f"(c0), "+f"(c1), "+f"(c2), "+f"(c3)
        : "r"(a0), "r"(a1), "r"(a2), "r"(a3), "r"(b0), "r"(b1));
}
__device__ __forceinline__ void mma1688(float& c0, float& c1, float& c2, float& c3,
                                        unsigned a0, unsigned a1, unsigned b0) {
    asm("mma.sync.aligned.m16n8k8.row.col.f32.f16.f16.f32 "
        "{%0,%1,%2,%3},{%4,%5},{%6},{%0,%1,%2,%3};"
        : "+f"(c0), "+f"(c1), "+f"(c2), "+f"(c3)
        : "r"(a0), "r"(a1), "r"(b0));
}
__device__ __forceinline__ void ldmA(unsigned& r0, unsigned& r1, unsigned& r2, unsigned& r3,
                                     uint32_t addr) {
    asm volatile("ldmatrix.sync.aligned.m8n8.x4.shared.b16 {%0,%1,%2,%3},[%4];"
                 : "=r"(r0), "=r"(r1), "=r"(r2), "=r"(r3) : "r"(addr));
}
__device__ __forceinline__ void cp16(uint32_t dst, const float* src) {
    asm volatile("cp.async.cg.shared.global [%0],[%1],16;" :: "r"(dst), "l"(src));
}
__device__ __forceinline__ void cp_commit() {
    asm volatile("cp.async.commit_group;");
}
__device__ __forceinline__ void cp_wait1() {
    asm volatile("cp.async.wait_group 1;");
}
__device__ __forceinline__ void cp_wait0() {
    asm volatile("cp.async.wait_group 0;");
}

// ---------------------------------------------------------------------------
// Prep: fragment-ordered fp16 weights; Wg folded into W0, bias table c0f
// ---------------------------------------------------------------------------
__global__ void prep_frags(const float* __restrict__ Wg,
                           const float* __restrict__ bg,
                           const float* __restrict__ W0,
                           const float* __restrict__ W1,
                           const float* __restrict__ W2,
                           const float* __restrict__ W3) {
    int idx = blockIdx.x * blockDim.x + threadIdx.x;
    if (idx < 512 * 32) {                       // W0f (folded): K=8, N=16
        int m = idx >> 5, lane = idx & 31;
        int k0 = (lane & 3) * 2, n = lane >> 2;
        const float* src = W0 + m * 128;        // [g][h]
        float g0 = Wg[m * 8 + k0], g1 = Wg[m * 8 + k0 + 1];
        __half2 f0 = __floats2half2_rn(g0 * src[k0 * 16 + n],
                                       g1 * src[(k0 + 1) * 16 + n]);
        __half2 f1 = __floats2half2_rn(g0 * src[k0 * 16 + n + 8],
                                       g1 * src[(k0 + 1) * 16 + n + 8]);
        uint2 v; v.x = h2bits(f0); v.y = h2bits(f1);
        g_W0f[idx] = v;
        return;
    }
    int t = idx - 512 * 32;
    if (t < 512 * 4) {                          // c0f: bias in C-frag order
        int m = t >> 2, qq = t & 3;
        float4 o;
        float s0 = 0.f, s1 = 0.f, s2 = 0.f, s3 = 0.f;
#pragma unroll
        for (int g = 0; g < 8; ++g) {
            float b = bg[m * 8 + g];
            const float* wr = W0 + m * 128 + g * 16;
            s0 += b * wr[qq * 2];     s1 += b * wr[qq * 2 + 1];
            s2 += b * wr[qq * 2 + 8]; s3 += b * wr[qq * 2 + 9];
        }
        o.x = s0; o.y = s1; o.z = s2; o.w = s3;
        g_c0f[t] = o;
        return;
    }
    t -= 512 * 4;
    if (t >= 73 * 32) return;
    int mod = t >> 5, lane = t & 31;
    const float* src; uint4* dst;
    if (mod < 64)      { src = W1 + mod * 2048;        dst = g_W1f + (size_t)(mod * 32 + lane) * 8; }
    else if (mod < 72) { src = W2 + (mod - 64) * 2048; dst = g_W2f + (size_t)((mod - 64) * 32 + lane) * 8; }
    else               { src = W3;                     dst = g_W3f + (size_t)lane * 8; }
#pragma unroll
    for (int kc = 0; kc < 8; ++kc) {
        uint4 o;
#pragma unroll
        for (int nh = 0; nh < 2; ++nh) {
            int k0 = kc * 16 + (lane & 3) * 2;
            int n  = nh * 8 + (lane >> 2);
            __half2 lo = __floats2half2_rn(src[k0 * 16 + n], src[(k0 + 1) * 16 + n]);
            __half2 hi = __floats2half2_rn(src[(k0 + 8) * 16 + n], src[(k0 + 9) * 16 + n]);
            if (nh == 0) { o.x = h2bits(lo); o.y = h2bits(hi); }
            else         { o.z = h2bits(lo); o.w = h2bits(hi); }
        }
        dst[kc] = o;
    }
}

// ---------------------------------------------------------------------------
extern __shared__ __align__(16) char smem_raw[];

__device__ __forceinline__ void gemm_16_128_16(uint32_t aAddr, const uint4* __restrict__ bp,
                                               float c[2][4]) {
    uint4 bv[8];
#pragma unroll
    for (int i = 0; i < 8; ++i) bv[i] = bp[i];
#pragma unroll
    for (int p = 0; p < 2; ++p)
#pragma unroll
        for (int q = 0; q < 4; ++q) c[p][q] = 0.f;
#pragma unroll
    for (int kc = 0; kc < 8; ++kc) {
        unsigned a0, a1, a2, a3;
        ldmA(a0, a1, a2, a3, aAddr + kc * 32);
        mma16816(c[0][0], c[0][1], c[0][2], c[0][3], a0, a1, a2, a3, bv[kc].x, bv[kc].y);
        mma16816(c[1][0], c[1][1], c[1][2], c[1][3], a0, a1, a2, a3, bv[kc].z, bv[kc].w);
    }
}

__device__ __forceinline__ void store_sig_half(char* base, int strideB, int colBase,
                                               int lane, float c[2][4]) {
    int r0 = lane >> 2, cB = colBase + (lane & 3) * 2;
#pragma unroll
    for (int nh = 0; nh < 2; ++nh) {
        __half2 lo = __floats2half2_rn(sigmoidf_(c[nh][0]), sigmoidf_(c[nh][1]));
        __half2 hi = __floats2half2_rn(sigmoidf_(c[nh][2]), sigmoidf_(c[nh][3]));
        *(__half2*)(base + r0 * strideB + (cB + nh * 8) * 2) = lo;
        *(__half2*)(base + (r0 + 8) * strideB + (cB + nh * 8) * 2) = hi;
    }
}

__global__ void __launch_bounds__(NTHREADS, 2)
fused_kernel(const float* __restrict__ x,
             const float* __restrict__ Wf,
             float* __restrict__ out) {
    const int tid  = threadIdx.x;
    const int lane = tid & 31;
    const int w    = tid >> 5;          // warp 0..7
    const int b0   = blockIdx.x * TILE_B;

    const uint32_t sbase = (uint32_t)__cvta_generic_to_shared(smem_raw);

    const int r0 = lane >> 2;           // batch row (first of pair)
    const int q2 = (lane & 3) * 2;      // col pair within frag

    // staging: this lane copies rows g*4 + (lane>>3), col segment (lane&7)*4 (+h*32)
    const int srow = lane >> 3;         // 0..3 (within row-group of 4)
    const int scol = (lane & 7) * 4;    // float offset
    const uint32_t xsbase = sbase + OFB_XS + w * 2 * XS_BUFB;
    const float* xg = x + ((size_t)b0 << 12) + w * 64;

    // issue stage for s2=0
    {
        const float* src = xg;
        uint32_t dst = xsbase;
#pragma unroll
        for (int g = 0; g < 4; ++g)
#pragma unroll
            for (int h = 0; h < 2; ++h)
                cp16(dst + ((g * 4 + srow) * XROW_F + h * 32 + scol) * 4,
                     src + ((size_t)(g * 4 + srow) << 12) + h * 32 + scol);
        cp_commit();
    }

#pragma unroll 1
    for (int s2 = 0; s2 < 8; ++s2) {
        // issue next stage before waiting on current (overlap DRAM with compute)
        if (s2 < 7) {
            const float* src = xg + (s2 + 1) * 512;
            uint32_t dst = xsbase + ((s2 + 1) & 1) * XS_BUFB;
#pragma unroll
            for (int g = 0; g < 4; ++g)
#pragma unroll
                for (int h = 0; h < 2; ++h)
                    cp16(dst + ((g * 4 + srow) * XROW_F + h * 32 + scol) * 4,
                         src + ((size_t)(g * 4 + srow) << 12) + h * 32 + scol);
            cp_commit();
            cp_wait1();    // current stage (s2) complete
        } else {
            cp_wait0();
        }
        __syncwarp();

        // prefetch this subtree's W1 fragments (L2-resident)
        uint4 bv[8];
        {
            const uint4* bp = g_W1f + (size_t)((s2 * 8 + w) * 32 + lane) * 8;
#pragma unroll
            for (int kc = 0; kc < 8; ++kc) bv[kc] = bp[kc];
        }

        // read x A-frags from staged smem + convert to fp16
        const float* xs = (const float*)(smem_raw + OFB_XS + (w * 2 + (s2 & 1)) * XS_BUFB);
        unsigned av0[8], av1[8];
#pragma unroll
        for (int mm = 0; mm < 8; ++mm) {
            float2 va = *(const float2*)(xs + r0 * XROW_F + mm * 8 + q2);
            float2 vb = *(const float2*)(xs + (r0 + 8) * XROW_F + mm * 8 + q2);
            av0[mm] = h2bits(__floats2half2_rn(va.x, va.y));
            av1[mm] = h2bits(__floats2half2_rn(vb.x, vb.y));
        }

        float acc[2][4];
#pragma unroll
        for (int p = 0; p < 2; ++p)
#pragma unroll
            for (int q = 0; q < 4; ++q) acc[p][q] = 0.f;

        // fused level-0 -> level-1: leaf mm's C-frag is level-1 chunk mm's A-frag
#pragma unroll
        for (int mm = 0; mm < 8; ++mm) {
            const int m = s2 * 64 + w * 8 + mm;
            float4 cf = g_c0f[m * 4 + (lane & 3)];
            uint2 bf = g_W0f[m * 32 + lane];
            float c0[4] = {cf.x, cf.y, cf.x, cf.y};
            float c1[4] = {cf.z, cf.w, cf.z, cf.w};
            mma1688(c0[0], c0[1], c0[2], c0[3], av0[mm], av1[mm], bf.x);
            mma1688(c1[0], c1[1], c1[2], c1[3], av0[mm], av1[mm], bf.y);
            unsigned f0 = h2bits(__floats2half2_rn(sigmoidf_(c0[0]), sigmoidf_(c0[1])));
            unsigned f1 = h2bits(__floats2half2_rn(sigmoidf_(c0[2]), sigmoidf_(c0[3])));
            unsigned f2 = h2bits(__floats2half2_rn(sigmoidf_(c1[0]), sigmoidf_(c1[1])));
            unsigned f3 = h2bits(__floats2half2_rn(sigmoidf_(c1[2]), sigmoidf_(c1[3])));
            mma16816(acc[0][0], acc[0][1], acc[0][2], acc[0][3],
                     f0, f1, f2, f3, bv[mm].x, bv[mm].y);
            mma16816(acc[1][0], acc[1][1], acc[1][2], acc[1][3],
                     f0, f1, f2, f3, bv[mm].z, bv[mm].w);
        }
        store_sig_half(smem_raw + OFB_H1, SH1_STRB, s2 * 128 + w * 16, lane, acc);
    }
    __syncthreads();   // H1 complete (cross-warp consumption next)

    // ---- Level 2: warp w = subtree w ----
    {
        uint32_t aAddr = sbase + OFB_H1 + (lane & 15) * SH1_STRB
                       + (w * 128 + ((lane >> 4) * 8)) * 2;
        float c[2][4];
        gemm_16_128_16(aAddr, g_W2f + (size_t)(w * 32 + lane) * 8, c);
        store_sig_half(smem_raw + OFB_H2, SH2_STRB, w * 16, lane, c);
    }
    __syncthreads();   // H2 complete

    // ---- Root (warp 0): [16,128]@[128,16], sigmoid, dot Wf, reduce ----
    if (w == 0) {
        uint32_t aAddr = sbase + OFB_H2 + (lane & 15) * SH2_STRB + ((lane >> 4) * 8) * 2;
        float c[2][4];
        gemm_16_128_16(aAddr, g_W3f + (size_t)lane * 8, c);
        float t0 = 0.f, t1 = 0.f;
#pragma unroll
        for (int nh = 0; nh < 2; ++nh) {
            float2 wf = __ldg((const float2*)(Wf + nh * 8 + q2));
            t0 += sigmoidf_(c[nh][0]) * wf.x + sigmoidf_(c[nh][1]) * wf.y;
            t1 += sigmoidf_(c[nh][2]) * wf.x + sigmoidf_(c[nh][3]) * wf.y;
        }
        t0 += __shfl_xor_sync(0xffffffffu, t0, 1);
        t0 += __shfl_xor_sync(0xffffffffu, t0, 2);
        t1 += __shfl_xor_sync(0xffffffffu, t1, 1);
        t1 += __shfl_xor_sync(0xffffffffu, t1, 2);
        if ((lane & 3) == 0) {
            out[b0 + r0] = t0;
            out[b0 + 8 + r0] = t1;
        }
    }
}

// ---------------------------------------------------------------------------
extern "C" void kernel_launch(void* const* d_in, const int* in_sizes, int n_in,
                              void* d_out, int out_size) {
    const float* x  = (const float*)d_in[0];
    const float* Wg = (const float*)d_in[1];
    const float* bg = (const float*)d_in[2];
    const float* W0 = (const float*)d_in[3];
    const float* W1 = (const float*)d_in[4];
    const float* W2 = (const float*)d_in[5];
    const float* W3 = (const float*)d_in[6];
    const float* Wf = (const float*)d_in[7];
    float* out = (float*)d_out;

    cudaFuncSetAttribute(fused_kernel,
                         cudaFuncAttributeMaxDynamicSharedMemorySize, SMEM_BYTES);

    prep_frags<<<82, 256>>>(Wg, bg, W0, W1, W2, W3);
    fused_kernel<<<NBLOCKS, NTHREADS, SMEM_BYTES>>>(x, Wf, out);
}

// round 15
// speedup vs baseline: 1.0515x; 1.0515x over previous
#include <cuda_runtime.h>
#include <cuda_fp16.h>
#include <cstdint>

#define NTHREADS 256
#define TILE_B   16
#define NBLOCKS  (4096 / TILE_B)   // 256

// smem: H1 [16][1032]h, H2 [16][136]h
#define OFB_H1  0
#define OFB_H2  33024
#define SMEM_BYTES 37376
#define SH1_STRB 2064
#define SH2_STRB 272

// Fragment-ordered weights
__device__ __align__(16) uint2  g_W0f[512 * 32];     // folded Wg*W0, b-frag order
__device__ __align__(16) float4 g_c0f[512 * 4];      // bias c0 in c-frag order
__device__ __align__(16) uint4  g_W1f[64 * 32 * 8];
__device__ __align__(16) uint4  g_W2f[8 * 32 * 8];
__device__ __align__(16) uint4  g_W3f[32 * 8];

__device__ __forceinline__ float sigmoidf_(float v) {
    float t;
    asm("tanh.approx.f32 %0, %1;" : "=f"(t) : "f"(v * 0.5f));
    return fmaf(t, 0.5f, 0.5f);
}
__device__ __forceinline__ unsigned h2bits(__half2 h) { return *(unsigned*)&h; }

// packed sigmoid: returns half2 bits of sigmoid(a), sigmoid(b)
__device__ __forceinline__ unsigned sig2(float a, float b) {
    __half2 hhalf = __float2half2_rn(0.5f);
    __half2 h = __hmul2(__floats2half2_rn(a, b), hhalf);
    unsigned hv = h2bits(h), t;
    asm("tanh.approx.f16x2 %0, %1;" : "=r"(t) : "r"(hv));
    __half2 r = __hfma2(*(__half2*)&t, hhalf, hhalf);
    return h2bits(r);
}

__device__ __forceinline__ void mma16816(float& c0, float& c1, float& c2, float& c3,
                                         unsigned a0, unsigned a1, unsigned a2, unsigned a3,
                                         unsigned b0, unsigned b1) {
    asm("mma.sync.aligned.m16n8k16.row.col.f32.f16.f16.f32 "
        "{%0,%1,%2,%3},{%4,%5,%6,%7},{%8,%9},{%0,%1,%2,%3};"
        : "+f"(c0), "+f"(c1), "+f"(c2), "+f"(c3)
        : "r"(a0), "r"(a1), "r"(a2), "r"(a3), "r"(b0), "r"(b1));
}
__device__ __forceinline__ void mma1688(float& c0, float& c1, float& c2, float& c3,
                                        unsigned a0, unsigned a1, unsigned b0) {
    asm("mma.sync.aligned.m16n8k8.row.col.f32.f16.f16.f32 "
        "{%0,%1,%2,%3},{%4,%5},{%6},{%0,%1,%2,%3};"
        : "+f"(c0), "+f"(c1), "+f"(c2), "+f"(c3)
        : "r"(a0), "r"(a1), "r"(b0));
}
__device__ __forceinline__ void ldmA(unsigned& r0, unsigned& r1, unsigned& r2, unsigned& r3,
                                     uint32_t addr) {
    asm volatile("ldmatrix.sync.aligned.m8n8.x4.shared.b16 {%0,%1,%2,%3},[%4];"
                 : "=r"(r0), "=r"(r1), "=r"(r2), "=r"(r3) : "r"(addr));
}

// ---------------------------------------------------------------------------
// Prep: fragment-ordered fp16 weights; Wg folded into W0, bias table c0f
// ---------------------------------------------------------------------------
__global__ void prep_frags(const float* __restrict__ Wg,
                           const float* __restrict__ bg,
                           const float* __restrict__ W0,
                           const float* __restrict__ W1,
                           const float* __restrict__ W2,
                           const float* __restrict__ W3) {
    int idx = blockIdx.x * blockDim.x + threadIdx.x;
    if (idx < 512 * 32) {                       // W0f (folded): K=8, N=16
        int m = idx >> 5, lane = idx & 31;
        int k0 = (lane & 3) * 2, n = lane >> 2;
        const float* src = W0 + m * 128;        // [g][h]
        float g0 = Wg[m * 8 + k0], g1 = Wg[m * 8 + k0 + 1];
        __half2 f0 = __floats2half2_rn(g0 * src[k0 * 16 + n],
                                       g1 * src[(k0 + 1) * 16 + n]);
        __half2 f1 = __floats2half2_rn(g0 * src[k0 * 16 + n + 8],
                                       g1 * src[(k0 + 1) * 16 + n + 8]);
        uint2 v; v.x = h2bits(f0); v.y = h2bits(f1);
        g_W0f[idx] = v;
        return;
    }
    int t = idx - 512 * 32;
    if (t < 512 * 4) {                          // c0f: bias in C-frag order
        int m = t >> 2, qq = t & 3;
        float4 o;
        float s0 = 0.f, s1 = 0.f, s2 = 0.f, s3 = 0.f;
#pragma unroll
        for (int g = 0; g < 8; ++g) {
            float b = bg[m * 8 + g];
            const float* wr = W0 + m * 128 + g * 16;
            s0 += b * wr[qq * 2];     s1 += b * wr[qq * 2 + 1];
            s2 += b * wr[qq * 2 + 8]; s3 += b * wr[qq * 2 + 9];
        }
        o.x = s0; o.y = s1; o.z = s2; o.w = s3;
        g_c0f[t] = o;
        return;
    }
    t -= 512 * 4;
    if (t >= 73 * 32) return;
    int mod = t >> 5, lane = t & 31;
    const float* src; uint4* dst;
    if (mod < 64)      { src = W1 + mod * 2048;        dst = g_W1f + (size_t)(mod * 32 + lane) * 8; }
    else if (mod < 72) { src = W2 + (mod - 64) * 2048; dst = g_W2f + (size_t)((mod - 64) * 32 + lane) * 8; }
    else               { src = W3;                     dst = g_W3f + (size_t)lane * 8; }
#pragma unroll
    for (int kc = 0; kc < 8; ++kc) {
        uint4 o;
#pragma unroll
        for (int nh = 0; nh < 2; ++nh) {
            int k0 = kc * 16 + (lane & 3) * 2;
            int n  = nh * 8 + (lane >> 2);
            __half2 lo = __floats2half2_rn(src[k0 * 16 + n], src[(k0 + 1) * 16 + n]);
            __half2 hi = __floats2half2_rn(src[(k0 + 8) * 16 + n], src[(k0 + 9) * 16 + n]);
            if (nh == 0) { o.x = h2bits(lo); o.y = h2bits(hi); }
            else         { o.z = h2bits(lo); o.w = h2bits(hi); }
        }
        dst[kc] = o;
    }
}

// ---------------------------------------------------------------------------
extern __shared__ __align__(16) char smem_raw[];

__device__ __forceinline__ void gemm_16_128_16(uint32_t aAddr, const uint4* __restrict__ bp,
                                               float c[2][4]) {
    uint4 bv[8];
#pragma unroll
    for (int i = 0; i < 8; ++i) bv[i] = bp[i];
#pragma unroll
    for (int p = 0; p < 2; ++p)
#pragma unroll
        for (int q = 0; q < 4; ++q) c[p][q] = 0.f;
#pragma unroll
    for (int kc = 0; kc < 8; ++kc) {
        unsigned a0, a1, a2, a3;
        ldmA(a0, a1, a2, a3, aAddr + kc * 32);
        mma16816(c[0][0], c[0][1], c[0][2], c[0][3], a0, a1, a2, a3, bv[kc].x, bv[kc].y);
        mma16816(c[1][0], c[1][1], c[1][2], c[1][3], a0, a1, a2, a3, bv[kc].z, bv[kc].w);
    }
}

__device__ __forceinline__ void store_sig_half(char* base, int strideB, int colBase,
                                               int lane, float c[2][4]) {
    int r0 = lane >> 2, cB = colBase + (lane & 3) * 2;
#pragma unroll
    for (int nh = 0; nh < 2; ++nh) {
        unsigned lo = sig2(c[nh][0], c[nh][1]);
        unsigned hi = sig2(c[nh][2], c[nh][3]);
        *(unsigned*)(base + r0 * strideB + (cB + nh * 8) * 2) = lo;
        *(unsigned*)(base + (r0 + 8) * strideB + (cB + nh * 8) * 2) = hi;
    }
}

__global__ void __launch_bounds__(NTHREADS, 2)
fused_kernel(const float* __restrict__ x,
             const float* __restrict__ Wf,
             float* __restrict__ out) {
    const int tid  = threadIdx.x;
    const int lane = tid & 31;
    const int w    = tid >> 5;          // warp 0..7
    const int b0   = blockIdx.x * TILE_B;

    const uint32_t sbase = (uint32_t)__cvta_generic_to_shared(smem_raw);

    const int r0 = lane >> 2;           // batch row (first of pair)
    const int q2 = (lane & 3) * 2;      // col pair within frag

    const size_t rowA = ((size_t)(b0 + r0)) << 12;
    const size_t rowB = rowA + (8ull << 12);
    const float* xpA = x + rowA + w * 64 + q2;
    const float* xpB = x + rowB + w * 64 + q2;

    float2 xa[8], xb[8];
#pragma unroll
    for (int mm = 0; mm < 8; ++mm) {
        xa[mm] = *(const float2*)(xpA + mm * 8);
        xb[mm] = *(const float2*)(xpB + mm * 8);
    }

#pragma unroll 1
    for (int s2 = 0; s2 < 8; ++s2) {
        // convert current x to fp16 A-frags (frees xa/xb for next prefetch)
        unsigned av0[8], av1[8];
#pragma unroll
        for (int mm = 0; mm < 8; ++mm) {
            av0[mm] = h2bits(__floats2half2_rn(xa[mm].x, xa[mm].y));
            av1[mm] = h2bits(__floats2half2_rn(xb[mm].x, xb[mm].y));
        }
        // prefetch next subtree's x (long latency, covered by MMA chain below)
        if (s2 < 7) {
            const float* pA = xpA + (s2 + 1) * 512;
            const float* pB = xpB + (s2 + 1) * 512;
#pragma unroll
            for (int mm = 0; mm < 8; ++mm) {
                xa[mm] = *(const float2*)(pA + mm * 8);
                xb[mm] = *(const float2*)(pB + mm * 8);
            }
        }
        // prefetch this subtree's W1 fragments (L2-resident)
        uint4 bv[8];
        {
            const uint4* bp = g_W1f + (size_t)((s2 * 8 + w) * 32 + lane) * 8;
#pragma unroll
            for (int kc = 0; kc < 8; ++kc) bv[kc] = bp[kc];
        }

        float acc[2][4];
#pragma unroll
        for (int p = 0; p < 2; ++p)
#pragma unroll
            for (int q = 0; q < 4; ++q) acc[p][q] = 0.f;

        // fused level-0 -> level-1: leaf mm's C-frag is level-1 chunk mm's A-frag
#pragma unroll
        for (int mm = 0; mm < 8; ++mm) {
            const int m = s2 * 64 + w * 8 + mm;
            float4 cf = g_c0f[m * 4 + (lane & 3)];
            uint2 bf = g_W0f[m * 32 + lane];
            float c0[4] = {cf.x, cf.y, cf.x, cf.y};
            float c1[4] = {cf.z, cf.w, cf.z, cf.w};
            mma1688(c0[0], c0[1], c0[2], c0[3], av0[mm], av1[mm], bf.x);
            mma1688(c1[0], c1[1], c1[2], c1[3], av0[mm], av1[mm], bf.y);
            unsigned f0 = sig2(c0[0], c0[1]);
            unsigned f1 = sig2(c0[2], c0[3]);
            unsigned f2 = sig2(c1[0], c1[1]);
            unsigned f3 = sig2(c1[2], c1[3]);
            mma16816(acc[0][0], acc[0][1], acc[0][2], acc[0][3],
                     f0, f1, f2, f3, bv[mm].x, bv[mm].y);
            mma16816(acc[1][0], acc[1][1], acc[1][2], acc[1][3],
                     f0, f1, f2, f3, bv[mm].z, bv[mm].w);
        }
        store_sig_half(smem_raw + OFB_H1, SH1_STRB, s2 * 128 + w * 16, lane, acc);
    }
    __syncthreads();   // H1 complete (cross-warp consumption next)

    // ---- Level 2: warp w = subtree w ----
    {
        uint32_t aAddr = sbase + OFB_H1 + (lane & 15) * SH1_STRB
                       + (w * 128 + ((lane >> 4) * 8)) * 2;
        float c[2][4];
        gemm_16_128_16(aAddr, g_W2f + (size_t)(w * 32 + lane) * 8, c);
        store_sig_half(smem_raw + OFB_H2, SH2_STRB, w * 16, lane, c);
    }
    __syncthreads();   // H2 complete

    // ---- Root (warp 0): [16,128]@[128,16], sigmoid, dot Wf, reduce ----
    if (w == 0) {
        uint32_t aAddr = sbase + OFB_H2 + (lane & 15) * SH2_STRB + ((lane >> 4) * 8) * 2;
        float c[2][4];
        gemm_16_128_16(aAddr, g_W3f + (size_t)lane * 8, c);
        float t0 = 0.f, t1 = 0.f;
#pragma unroll
        for (int nh = 0; nh < 2; ++nh) {
            float2 wf = __ldg((const float2*)(Wf + nh * 8 + q2));
            t0 += sigmoidf_(c[nh][0]) * wf.x + sigmoidf_(c[nh][1]) * wf.y;
            t1 += sigmoidf_(c[nh][2]) * wf.x + sigmoidf_(c[nh][3]) * wf.y;
        }
        t0 += __shfl_xor_sync(0xffffffffu, t0, 1);
        t0 += __shfl_xor_sync(0xffffffffu, t0, 2);
        t1 += __shfl_xor_sync(0xffffffffu, t1, 1);
        t1 += __shfl_xor_sync(0xffffffffu, t1, 2);
        if ((lane & 3) == 0) {
            out[b0 + r0] = t0;
            out[b0 + 8 + r0] = t1;
        }
    }
}

// ---------------------------------------------------------------------------
extern "C" void kernel_launch(void* const* d_in, const int* in_sizes, int n_in,
                              void* d_out, int out_size) {
    const float* x  = (const float*)d_in[0];
    const float* Wg = (const float*)d_in[1];
    const float* bg = (const float*)d_in[2];
    const float* W0 = (const float*)d_in[3];
    const float* W1 = (const float*)d_in[4];
    const float* W2 = (const float*)d_in[5];
    const float* W3 = (const float*)d_in[6];
    const float* Wf = (const float*)d_in[7];
    float* out = (float*)d_out;

    cudaFuncSetAttribute(fused_kernel,
                         cudaFuncAttributeMaxDynamicSharedMemorySize, SMEM_BYTES);

    prep_frags<<<82, 256>>>(Wg, bg, W0, W1, W2, W3);
    fused_kernel<<<NBLOCKS, NTHREADS, SMEM_BYTES>>>(x, Wf, out);
}

// round 16
// speedup vs baseline: 1.1634x; 1.1064x over previous
#include <cuda_runtime.h>
#include <cuda_fp16.h>
#include <cstdint>

#define NTHREADS 256
#define TILE_B   16
#define NBLOCKS  (4096 / TILE_B)   // 256

// smem layout (bytes)
#define XROW_B  176                // fp16 row stride (44 words ≡ 12 mod 32: ldmatrix conflict-free)
#define XS_BUFB (16 * XROW_B)      // 2816 B per warp per buffer
#define OFB_XS  0                  // 8 warps * 2 bufs * 2816 = 45056
#define OFB_H1  45056              // half [16][1032] = 33024
#define OFB_H2  78080              // half [16][136]  = 4352
#define SMEM_BYTES 82432
#define SH1_STRB 2064
#define SH2_STRB 272

// Fragment-ordered weights
__device__ __align__(16) uint2  g_W0f[512 * 32];     // folded Wg*W0, b-frag order
__device__ __align__(16) float4 g_c0f[512 * 4];      // bias c0 in c-frag order
__device__ __align__(16) uint4  g_W1f[64 * 32 * 8];
__device__ __align__(16) uint4  g_W2f[8 * 32 * 8];
__device__ __align__(16) uint4  g_W3f[32 * 8];

__device__ __forceinline__ float sigmoidf_(float v) {
    float t;
    asm("tanh.approx.f32 %0, %1;" : "=f"(t) : "f"(v * 0.5f));
    return fmaf(t, 0.5f, 0.5f);
}
__device__ __forceinline__ unsigned h2bits(__half2 h) { return *(unsigned*)&h; }

// packed sigmoid: returns half2 bits of sigmoid(a), sigmoid(b)
__device__ __forceinline__ unsigned sig2(float a, float b) {
    __half2 hhalf = __float2half2_rn(0.5f);
    __half2 h = __hmul2(__floats2half2_rn(a, b), hhalf);
    unsigned hv = h2bits(h), t;
    asm("tanh.approx.f16x2 %0, %1;" : "=r"(t) : "r"(hv));
    __half2 r = __hfma2(*(__half2*)&t, hhalf, hhalf);
    return h2bits(r);
}

__device__ __forceinline__ void mma16816(float& c0, float& c1, float& c2, float& c3,
                                         unsigned a0, unsigned a1, unsigned a2, unsigned a3,
                                         unsigned b0, unsigned b1) {
    asm("mma.sync.aligned.m16n8k16.row.col.f32.f16.f16.f32 "
        "{%0,%1,%2,%3},{%4,%5,%6,%7},{%8,%9},{%0,%1,%2,%3};"
        : "+f"(c0), "+f"(c1), "+f"(c2), "+f"(c3)
        : "r"(a0), "r"(a1), "r"(a2), "r"(a3), "r"(b0), "r"(b1));
}
__device__ __forceinline__ void mma1688(float& c0, float& c1, float& c2, float& c3,
                                        unsigned a0, unsigned a1, unsigned b0) {
    asm("mma.sync.aligned.m16n8k8.row.col.f32.f16.f16.f32 "
        "{%0,%1,%2,%3},{%4,%5},{%6},{%0,%1,%2,%3};"
        : "+f"(c0), "+f"(c1), "+f"(c2), "+f"(c3)
        : "r"(a0), "r"(a1), "r"(b0));
}
__device__ __forceinline__ void ldmA(unsigned& r0, unsigned& r1, unsigned& r2, unsigned& r3,
                                     uint32_t addr) {
    asm volatile("ldmatrix.sync.aligned.m8n8.x4.shared.b16 {%0,%1,%2,%3},[%4];"
                 : "=r"(r0), "=r"(r1), "=r"(r2), "=r"(r3) : "r"(addr));
}
__device__ __forceinline__ void ldmA2(unsigned& r0, unsigned& r1, uint32_t addr) {
    asm volatile("ldmatrix.sync.aligned.m8n8.x2.shared.b16 {%0,%1},[%2];"
                 : "=r"(r0), "=r"(r1) : "r"(addr));
}

// ---------------------------------------------------------------------------
// Prep: fragment-ordered fp16 weights; Wg folded into W0, bias table c0f
// ---------------------------------------------------------------------------
__global__ void prep_frags(const float* __restrict__ Wg,
                           const float* __restrict__ bg,
                           const float* __restrict__ W0,
                           const float* __restrict__ W1,
                           const float* __restrict__ W2,
                           const float* __restrict__ W3) {
    int idx = blockIdx.x * blockDim.x + threadIdx.x;
    if (idx < 512 * 32) {                       // W0f (folded): K=8, N=16
        int m = idx >> 5, lane = idx & 31;
        int k0 = (lane & 3) * 2, n = lane >> 2;
        const float* src = W0 + m * 128;        // [g][h]
        float g0 = Wg[m * 8 + k0], g1 = Wg[m * 8 + k0 + 1];
        __half2 f0 = __floats2half2_rn(g0 * src[k0 * 16 + n],
                                       g1 * src[(k0 + 1) * 16 + n]);
        __half2 f1 = __floats2half2_rn(g0 * src[k0 * 16 + n + 8],
                                       g1 * src[(k0 + 1) * 16 + n + 8]);
        uint2 v; v.x = h2bits(f0); v.y = h2bits(f1);
        g_W0f[idx] = v;
        return;
    }
    int t = idx - 512 * 32;
    if (t < 512 * 4) {                          // c0f: bias in C-frag order
        int m = t >> 2, qq = t & 3;
        float4 o;
        float s0 = 0.f, s1 = 0.f, s2 = 0.f, s3 = 0.f;
#pragma unroll
        for (int g = 0; g < 8; ++g) {
            float b = bg[m * 8 + g];
            const float* wr = W0 + m * 128 + g * 16;
            s0 += b * wr[qq * 2];     s1 += b * wr[qq * 2 + 1];
            s2 += b * wr[qq * 2 + 8]; s3 += b * wr[qq * 2 + 9];
        }
        o.x = s0; o.y = s1; o.z = s2; o.w = s3;
        g_c0f[t] = o;
        return;
    }
    t -= 512 * 4;
    if (t >= 73 * 32) return;
    int mod = t >> 5, lane = t & 31;
    const float* src; uint4* dst;
    if (mod < 64)      { src = W1 + mod * 2048;        dst = g_W1f + (size_t)(mod * 32 + lane) * 8; }
    else if (mod < 72) { src = W2 + (mod - 64) * 2048; dst = g_W2f + (size_t)((mod - 64) * 32 + lane) * 8; }
    else               { src = W3;                     dst = g_W3f + (size_t)lane * 8; }
#pragma unroll
    for (int kc = 0; kc < 8; ++kc) {
        uint4 o;
#pragma unroll
        for (int nh = 0; nh < 2; ++nh) {
            int k0 = kc * 16 + (lane & 3) * 2;
            int n  = nh * 8 + (lane >> 2);
            __half2 lo = __floats2half2_rn(src[k0 * 16 + n], src[(k0 + 1) * 16 + n]);
            __half2 hi = __floats2half2_rn(src[(k0 + 8) * 16 + n], src[(k0 + 9) * 16 + n]);
            if (nh == 0) { o.x = h2bits(lo); o.y = h2bits(hi); }
            else         { o.z = h2bits(lo); o.w = h2bits(hi); }
        }
        dst[kc] = o;
    }
}

// ---------------------------------------------------------------------------
extern __shared__ __align__(16) char smem_raw[];

__device__ __forceinline__ void gemm_16_128_16(uint32_t aAddr, const uint4* __restrict__ bp,
                                               float c[2][4]) {
    uint4 bv[8];
#pragma unroll
    for (int i = 0; i < 8; ++i) bv[i] = bp[i];
#pragma unroll
    for (int p = 0; p < 2; ++p)
#pragma unroll
        for (int q = 0; q < 4; ++q) c[p][q] = 0.f;
#pragma unroll
    for (int kc = 0; kc < 8; ++kc) {
        unsigned a0, a1, a2, a3;
        ldmA(a0, a1, a2, a3, aAddr + kc * 32);
        mma16816(c[0][0], c[0][1], c[0][2], c[0][3], a0, a1, a2, a3, bv[kc].x, bv[kc].y);
        mma16816(c[1][0], c[1][1], c[1][2], c[1][3], a0, a1, a2, a3, bv[kc].z, bv[kc].w);
    }
}

__device__ __forceinline__ void store_sig_half(char* base, int strideB, int colBase,
                                               int lane, float c[2][4]) {
    int r0 = lane >> 2, cB = colBase + (lane & 3) * 2;
#pragma unroll
    for (int nh = 0; nh < 2; ++nh) {
        unsigned lo = sig2(c[nh][0], c[nh][1]);
        unsigned hi = sig2(c[nh][2], c[nh][3]);
        *(unsigned*)(base + r0 * strideB + (cB + nh * 8) * 2) = lo;
        *(unsigned*)(base + (r0 + 8) * strideB + (cB + nh * 8) * 2) = hi;
    }
}

__global__ void __launch_bounds__(NTHREADS, 2)
fused_kernel(const float* __restrict__ x,
             const float* __restrict__ Wf,
             float* __restrict__ out) {
    const int tid  = threadIdx.x;
    const int lane = tid & 31;
    const int w    = tid >> 5;          // warp 0..7
    const int b0   = blockIdx.x * TILE_B;

    const uint32_t sbase = (uint32_t)__cvta_generic_to_shared(smem_raw);

    const int r0 = lane >> 2;           // batch row (first of pair)
    const int q2 = (lane & 3) * 2;      // col pair within frag

    // coalesced x staging: lane covers row xrow2 (2 rows per LDG), float4 col xcol
    const int xrow = lane >> 4;         // 0..1
    const int xcol = lane & 15;         // float4 index within 64-float slice
    const float* xgw = x + ((size_t)b0 << 12) + w * 64;     // warp's gene slice
    char* xbufs = smem_raw + OFB_XS + w * 2 * XS_BUFB;
    // ldmatrix row address (lanes 0..15 select rows)
    const uint32_t xldm = sbase + OFB_XS + w * 2 * XS_BUFB + (lane & 15) * XROW_B;

    uint4 xr[8];
    // prologue: load s2=0 (coalesced), convert+store to buf0
#pragma unroll
    for (int g = 0; g < 8; ++g)
        xr[g] = *(const uint4*)(xgw + ((size_t)(g * 2 + xrow) << 12) + xcol * 4);
#pragma unroll
    for (int g = 0; g < 8; ++g) {
        float4 f = *(float4*)&xr[g];
        uint2 st;
        st.x = h2bits(__floats2half2_rn(f.x, f.y));
        st.y = h2bits(__floats2half2_rn(f.z, f.w));
        *(uint2*)(xbufs + (g * 2 + xrow) * XROW_B + xcol * 8) = st;
    }
    __syncwarp();

#pragma unroll 1
    for (int s2 = 0; s2 < 8; ++s2) {
        // issue next subtree's coalesced loads (overlap with MMA chain)
        if (s2 < 7) {
            const float* src = xgw + (s2 + 1) * 512;
#pragma unroll
            for (int g = 0; g < 8; ++g)
                xr[g] = *(const uint4*)(src + ((size_t)(g * 2 + xrow) << 12) + xcol * 4);
        }
        // prefetch this subtree's W1 fragments (L2-resident)
        uint4 bv[8];
        {
            const uint4* bp = g_W1f + (size_t)((s2 * 8 + w) * 32 + lane) * 8;
#pragma unroll
            for (int kc = 0; kc < 8; ++kc) bv[kc] = bp[kc];
        }

        const uint32_t xa = xldm + (s2 & 1) * XS_BUFB;

        float acc[2][4];
#pragma unroll
        for (int p = 0; p < 2; ++p)
#pragma unroll
            for (int q = 0; q < 4; ++q) acc[p][q] = 0.f;

        // fused level-0 -> level-1: leaf mm's C-frag is level-1 chunk mm's A-frag
#pragma unroll
        for (int mm = 0; mm < 8; ++mm) {
            const int m = s2 * 64 + w * 8 + mm;
            unsigned av0, av1;
            ldmA2(av0, av1, xa + mm * 16);
            float4 cf = g_c0f[m * 4 + (lane & 3)];
            uint2 bf = g_W0f[m * 32 + lane];
            float c0[4] = {cf.x, cf.y, cf.x, cf.y};
            float c1[4] = {cf.z, cf.w, cf.z, cf.w};
            mma1688(c0[0], c0[1], c0[2], c0[3], av0, av1, bf.x);
            mma1688(c1[0], c1[1], c1[2], c1[3], av0, av1, bf.y);
            unsigned f0 = sig2(c0[0], c0[1]);
            unsigned f1 = sig2(c0[2], c0[3]);
            unsigned f2 = sig2(c1[0], c1[1]);
            unsigned f3 = sig2(c1[2], c1[3]);
            mma16816(acc[0][0], acc[0][1], acc[0][2], acc[0][3],
                     f0, f1, f2, f3, bv[mm].x, bv[mm].y);
            mma16816(acc[1][0], acc[1][1], acc[1][2], acc[1][3],
                     f0, f1, f2, f3, bv[mm].z, bv[mm].w);
        }
        store_sig_half(smem_raw + OFB_H1, SH1_STRB, s2 * 128 + w * 16, lane, acc);

        // convert + store next subtree's x into the other buffer
        if (s2 < 7) {
            char* dst = xbufs + ((s2 + 1) & 1) * XS_BUFB;
#pragma unroll
            for (int g = 0; g < 8; ++g) {
                float4 f = *(float4*)&xr[g];
                uint2 st;
                st.x = h2bits(__floats2half2_rn(f.x, f.y));
                st.y = h2bits(__floats2half2_rn(f.z, f.w));
                *(uint2*)(dst + (g * 2 + xrow) * XROW_B + xcol * 8) = st;
            }
        }
        __syncwarp();
    }
    __syncthreads();   // H1 complete (cross-warp consumption next)

    // ---- Level 2: warp w = subtree w ----
    {
        uint32_t aAddr = sbase + OFB_H1 + (lane & 15) * SH1_STRB
                       + (w * 128 + ((lane >> 4) * 8)) * 2;
        float c[2][4];
        gemm_16_128_16(aAddr, g_W2f + (size_t)(w * 32 + lane) * 8, c);
        store_sig_half(smem_raw + OFB_H2, SH2_STRB, w * 16, lane, c);
    }
    __syncthreads();   // H2 complete

    // ---- Root (warp 0): [16,128]@[128,16], sigmoid, dot Wf, reduce ----
    if (w == 0) {
        uint32_t aAddr = sbase + OFB_H2 + (lane & 15) * SH2_STRB + ((lane >> 4) * 8) * 2;
        float c[2][4];
        gemm_16_128_16(aAddr, g_W3f + (size_t)lane * 8, c);
        float t0 = 0.f, t1 = 0.f;
#pragma unroll
        for (int nh = 0; nh < 2; ++nh) {
            float2 wf = __ldg((const float2*)(Wf + nh * 8 + q2));
            t0 += sigmoidf_(c[nh][0]) * wf.x + sigmoidf_(c[nh][1]) * wf.y;
            t1 += sigmoidf_(c[nh][2]) * wf.x + sigmoidf_(c[nh][3]) * wf.y;
        }
        t0 += __shfl_xor_sync(0xffffffffu, t0, 1);
        t0 += __shfl_xor_sync(0xffffffffu, t0, 2);
        t1 += __shfl_xor_sync(0xffffffffu, t1, 1);
        t1 += __shfl_xor_sync(0xffffffffu, t1, 2);
        if ((lane & 3) == 0) {
            out[b0 + r0] = t0;
            out[b0 + 8 + r0] = t1;
        }
    }
}

// ---------------------------------------------------------------------------
extern "C" void kernel_launch(void* const* d_in, const int* in_sizes, int n_in,
                              void* d_out, int out_size) {
    const float* x  = (const float*)d_in[0];
    const float* Wg = (const float*)d_in[1];
    const float* bg = (const float*)d_in[2];
    const float* W0 = (const float*)d_in[3];
    const float* W1 = (const float*)d_in[4];
    const float* W2 = (const float*)d_in[5];
    const float* W3 = (const float*)d_in[6];
    const float* Wf = (const float*)d_in[7];
    float* out = (float*)d_out;

    cudaFuncSetAttribute(fused_kernel,
                         cudaFuncAttributeMaxDynamicSharedMemorySize, SMEM_BYTES);

    prep_frags<<<82, 256>>>(Wg, bg, W0, W1, W2, W3);
    fused_kernel<<<NBLOCKS, NTHREADS, SMEM_BYTES>>>(x, Wf, out);
}